// round 1
// baseline (speedup 1.0000x reference)
#include <cuda_runtime.h>

// ---------------------------------------------------------------------------
// Inverse DTCWT, 3 levels. N*C=128 images. yl (128,64,64) -> out (128,256,256)
// Stage A (per upsampling level): y1/y2 = colifilt(z|bands)   rows x2
// Stage B:                        z'    = rowifilt(y1,y2)     cols x2
// Stage C (final): y1/y2 = colfilter(z|bands, g0o/g1o)
// Stage D:         out   = rowfilter(y1,y2)
// Bands (lh,hl,hh) are computed on the fly from yh via c2q (never stored).
// ---------------------------------------------------------------------------

#define SQRT_HALF 0.70710678118654752440f

__constant__ float c_g0a[10] = {0.03516384f, 0.0f, -0.08832942f, 0.23389032f, 0.76027237f,
                                0.5875183f, 0.0f, -0.11430184f, 0.0f, 0.0f};
__constant__ float c_g0b[10] = {0.0f, 0.0f, -0.11430184f, 0.0f, 0.5875183f,
                                0.76027237f, 0.23389032f, -0.08832942f, 0.0f, 0.03516384f};
__constant__ float c_g1a[10] = {0.0f, 0.0f, -0.11430184f, 0.0f, 0.5875183f,
                                -0.76027237f, 0.23389032f, 0.08832942f, 0.0f, -0.03516384f};
__constant__ float c_g1b[10] = {-0.03516384f, 0.0f, 0.08832942f, 0.23389032f, -0.76027237f,
                                0.5875183f, 0.0f, -0.11430184f, 0.0f, 0.0f};
__constant__ float c_g0o[3]  = {0.35355339059327f, 0.70710678118655f, 0.35355339059327f};
__constant__ float c_g1o[5]  = {-0.08838834764832f, -0.17677669529664f, 0.53033008588991f,
                                -0.17677669529664f, -0.08838834764832f};

// Scratch (statically allocated; max footprint is the final 256x256 stage)
__device__ float g_y1[128 * 256 * 256];
__device__ float g_y2[128 * 256 * 256];
__device__ float g_z128[128 * 128 * 128];
__device__ float g_z256[128 * 256 * 256];

// symmetric pad (m=5) padded-index -> source-index, n = source length
__device__ __forceinline__ int symmap5(int p, int n) {
    if (p < 5) return 4 - p;
    p -= 5;
    if (p >= n) p = 2 * n - 1 - p;
    return p;
}
// general symmetric pad m
__device__ __forceinline__ int symmapM(int p, int m, int n) {
    if (p < m) return m - 1 - p;
    p -= m;
    if (p >= n) p = 2 * n - 1 - p;
    return p;
}

// c2q element (i,j) of band built from subbands (s1,s2). Band is (r,c); yh
// subbands are (r/2, c/2, 2). Layout: yh[((b*6+s)*rh + ii)*ch*2 + jj*2 + ri].
__device__ __forceinline__ float band_val(const float* __restrict__ yh, int b,
                                          int s1, int s2, int i, int j,
                                          int rh, int ch) {
    int ii = i >> 1, jj = j >> 1;
    int pi = i & 1, pj = j & 1;
    int ri = pi ^ pj;  // x1,x4 use real part; x2,x3 use imaginary part
    size_t o1 = ((size_t)(b * 6 + s1) * rh + ii) * (ch * 2) + jj * 2 + ri;
    size_t o2 = ((size_t)(b * 6 + s2) * rh + ii) * (ch * 2) + jj * 2 + ri;
    float w1 = __ldg(yh + o1);
    float w2 = __ldg(yh + o2);
    float v;
    if (!pi)      v = w1 + w2;   // x1 or x2
    else if (!pj) v = w1 - w2;   // x3 = w1i - w2i
    else          v = w2 - w1;   // x4 = w2r - w1r
    return v * SQRT_HALF;
}

// ---------------------------------------------------------------------------
// Stage A: fused column-direction colifilt of z (lowpass pair) + lh (highpass
// pair) -> y1, and hl (lowpass) + hh (highpass) -> y2.  z: (128,r,c).
// Outputs: (128, 2r, c).
// ---------------------------------------------------------------------------
__global__ void __launch_bounds__(256)
kA_ifilt_col(const float* __restrict__ z, const float* __restrict__ yh,
             float* __restrict__ y1, float* __restrict__ y2, int r, int c) {
    int idx = blockIdx.x * blockDim.x + threadIdx.x;
    int R2 = 2 * r;
    int total = 128 * R2 * c;
    if (idx >= total) return;
    int j = idx % c;
    int t = (idx / c) % R2;
    int b = idx / (c * R2);
    int n = t >> 2, q = t & 3;
    int rh = r >> 1, ch = c >> 1;

    const float* fl = (q & 1) ? c_g0a : c_g0b;
    const float* fh = (q & 1) ? c_g1a : c_g1b;
    int tap0 = (q < 2) ? 8 : 9;

    const float* zb = z + (size_t)b * r * c;
    float acc1 = 0.f, acc2 = 0.f;
#pragma unroll
    for (int k = 0; k < 5; k++) {
        float ftl = fl[tap0 - 2 * k];
        float fth = fh[tap0 - 2 * k];
        int pe = 1 + 2 * (n + k);           // xe padded index
        int po = 2 + 2 * (n + k);           // xo padded index
        int rowL = symmap5((q & 1) ? po : pe, r);  // lowpass source rows
        int rowH = symmap5((q & 1) ? pe : po, r);  // highpass source rows
        if (ftl != 0.f) {
            acc1 += ftl * __ldg(zb + (size_t)rowL * c + j);
            acc2 += ftl * band_val(yh, b, 2, 3, rowL, j, rh, ch);  // hl
        }
        if (fth != 0.f) {
            acc1 += fth * band_val(yh, b, 0, 5, rowH, j, rh, ch);  // lh
            acc2 += fth * band_val(yh, b, 1, 4, rowH, j, rh, ch);  // hh
        }
    }
    size_t o = ((size_t)b * R2 + t) * c + j;
    y1[o] = acc1;
    y2[o] = acc2;
}

// ---------------------------------------------------------------------------
// Stage B: z' = rowifilt(y1, lowpass pair) + rowifilt(y2, highpass pair).
// y1,y2: (128, R, c) -> z': (128, R, 2c)
// ---------------------------------------------------------------------------
__global__ void __launch_bounds__(256)
kB_ifilt_row(const float* __restrict__ y1, const float* __restrict__ y2,
             float* __restrict__ zo, int R, int c) {
    int idx = blockIdx.x * blockDim.x + threadIdx.x;
    int C2 = 2 * c;
    int total = 128 * R * C2;
    if (idx >= total) return;
    int u = idx % C2;
    int i = (idx / C2) % R;
    int b = idx / (C2 * R);
    int n = u >> 2, q = u & 3;

    const float* fl = (q & 1) ? c_g0a : c_g0b;
    const float* fh = (q & 1) ? c_g1a : c_g1b;
    int tap0 = (q < 2) ? 8 : 9;

    const float* r1 = y1 + ((size_t)b * R + i) * c;
    const float* r2 = y2 + ((size_t)b * R + i) * c;
    float acc = 0.f;
#pragma unroll
    for (int k = 0; k < 5; k++) {
        float ftl = fl[tap0 - 2 * k];
        float fth = fh[tap0 - 2 * k];
        int pe = 1 + 2 * (n + k);
        int po = 2 + 2 * (n + k);
        int colL = symmap5((q & 1) ? po : pe, c);
        int colH = symmap5((q & 1) ? pe : po, c);
        if (ftl != 0.f) acc += ftl * __ldg(r1 + colL);
        if (fth != 0.f) acc += fth * __ldg(r2 + colH);
    }
    zo[idx] = acc;
}

// ---------------------------------------------------------------------------
// Stage C: final-level column filters (non-decimating).
// y1 = colfilter(z,g0o)+colfilter(lh,g1o); y2 = colfilter(hl,g0o)+colfilter(hh,g1o)
// z: (128,R,C) ; yh0 subbands (R/2,C/2,2)
// ---------------------------------------------------------------------------
__global__ void __launch_bounds__(256)
kC_filt_col(const float* __restrict__ z, const float* __restrict__ yh,
            float* __restrict__ y1, float* __restrict__ y2, int R, int C) {
    int idx = blockIdx.x * blockDim.x + threadIdx.x;
    int total = 128 * R * C;
    if (idx >= total) return;
    int j = idx % C;
    int i = (idx / C) % R;
    int b = idx / (R * C);
    int rh = R >> 1, ch = C >> 1;

    const float* zb = z + (size_t)b * R * C;
    float a1 = 0.f, a2 = 0.f;
#pragma unroll
    for (int k = 0; k < 3; k++) {
        int s = symmapM(i + k, 1, R);
        float f = c_g0o[2 - k];
        a1 += f * __ldg(zb + (size_t)s * C + j);
        a2 += f * band_val(yh, b, 2, 3, s, j, rh, ch);  // hl
    }
#pragma unroll
    for (int k = 0; k < 5; k++) {
        int s = symmapM(i + k, 2, R);
        float f = c_g1o[4 - k];
        a1 += f * band_val(yh, b, 0, 5, s, j, rh, ch);  // lh
        a2 += f * band_val(yh, b, 1, 4, s, j, rh, ch);  // hh
    }
    y1[idx] = a1;
    y2[idx] = a2;
}

// ---------------------------------------------------------------------------
// Stage D: out = rowfilter(y1,g0o) + rowfilter(y2,g1o).  (128,R,C) fp32 out.
// ---------------------------------------------------------------------------
__global__ void __launch_bounds__(256)
kD_filt_row(const float* __restrict__ y1, const float* __restrict__ y2,
            float* __restrict__ out, int R, int C) {
    int idx = blockIdx.x * blockDim.x + threadIdx.x;
    int total = 128 * R * C;
    if (idx >= total) return;
    int j = idx % C;
    int i = (idx / C) % R;
    int b = idx / (R * C);

    const float* r1 = y1 + ((size_t)b * R + i) * C;
    const float* r2 = y2 + ((size_t)b * R + i) * C;
    float a = 0.f;
#pragma unroll
    for (int k = 0; k < 3; k++)
        a += c_g0o[2 - k] * __ldg(r1 + symmapM(j + k, 1, C));
#pragma unroll
    for (int k = 0; k < 5; k++)
        a += c_g1o[4 - k] * __ldg(r2 + symmapM(j + k, 2, C));
    out[idx] = a;
}

extern "C" void kernel_launch(void* const* d_in, const int* in_sizes, int n_in,
                              void* d_out, int out_size) {
    // Locate tensors by element count (robust to ordering).
    const float *yl = nullptr, *yh0 = nullptr, *yh1 = nullptr, *yh2 = nullptr;
    for (int i = 0; i < n_in; i++) {
        switch (in_sizes[i]) {
            case 524288:   yl  = (const float*)d_in[i]; break;  // 128*64*64
            case 25165824: yh0 = (const float*)d_in[i]; break;  // 128*6*128*128*2
            case 6291456:  yh1 = (const float*)d_in[i]; break;  // 128*6*64*64*2
            case 1572864:  yh2 = (const float*)d_in[i]; break;  // 128*6*32*32*2
            default: break;
        }
    }

    float *py1, *py2, *pz128, *pz256;
    cudaGetSymbolAddress((void**)&py1,   g_y1);
    cudaGetSymbolAddress((void**)&py2,   g_y2);
    cudaGetSymbolAddress((void**)&pz128, g_z128);
    cudaGetSymbolAddress((void**)&pz256, g_z256);

    const int T = 256;
    auto blocks = [](int total, int t) { return (total + t - 1) / t; };

    // Level with yh2: z (64,64) -> (128,128)
    kA_ifilt_col<<<blocks(128 * 128 * 64, T), T>>>(yl, yh2, py1, py2, 64, 64);
    kB_ifilt_row<<<blocks(128 * 128 * 128, T), T>>>(py1, py2, pz128, 128, 64);

    // Level with yh1: z (128,128) -> (256,256)
    kA_ifilt_col<<<blocks(128 * 256 * 128, T), T>>>(pz128, yh1, py1, py2, 128, 128);
    kB_ifilt_row<<<blocks(128 * 256 * 256, T), T>>>(py1, py2, pz256, 256, 128);

    // Final level with yh0 (non-decimating)
    kC_filt_col<<<blocks(128 * 256 * 256, T), T>>>(pz256, yh0, py1, py2, 256, 256);
    kD_filt_row<<<blocks(128 * 256 * 256, T), T>>>(py1, py2, (float*)d_out, 256, 256);
}

// round 2
// speedup vs baseline: 3.5824x; 3.5824x over previous
#include <cuda_runtime.h>

// ---------------------------------------------------------------------------
// Inverse DTCWT, 3 levels, phase-specialized. 128 images.
// Upsampling phases for output t = 4n+q (derived from colifilt, verified vs R1):
//   L = lowpass source, H = highpass source, window offsets around 2n:
//   out0 =  .2339*L[-2]+.5875*L[0]-.1143*L[+2]  -.7603*H[+1]+.0883*H[+3]-.0352*H[+5]
//   out1 =  .7603*L[+1]-.0883*L[+3]+.0352*L[+5] +.2339*H[-2]+.5875*H[0]-.1143*H[+2]
//   out2 =  .0352*L[-4]-.0883*L[-2]+.7603*L[0]  -.1143*H[-1]+.5875*H[+1]+.2339*H[+3]
//   out3 = -.1143*L[-1]+.5875*L[+1]+.2339*L[+3] -.0352*H[-4]+.0883*H[-2]-.7603*H[0]
// Window offsets union (both L and H): {-4,-2,0,2} ∪ {-1,1,3,5}  -> 8 loads each.
// ---------------------------------------------------------------------------

#define SH   0.70710678118654752440f
#define C_A  0.23389032f
#define C_B  0.5875183f
#define C_C  0.11430184f
#define C_D  0.76027237f
#define C_E  0.08832942f
#define C_F  0.03516384f

// final-level biorthogonal filters
#define G0   0.35355339059327f
#define G1   0.70710678118655f
#define Q_E  (-0.08838834764832f)
#define Q_D  (-0.17677669529664f)
#define Q_F  0.53033008588991f

// window index map: [0]=-4 [1]=-2 [2]=0 [3]=+2 [4]=-1 [5]=+1 [6]=+3 [7]=+5
#define LP0(L) ( C_A*L[1] + C_B*L[2] - C_C*L[3])
#define LP1(L) ( C_D*L[5] - C_E*L[6] + C_F*L[7])
#define LP2(L) ( C_F*L[0] - C_E*L[1] + C_D*L[2])
#define LP3(L) (-C_C*L[4] + C_B*L[5] + C_A*L[6])
#define HP0(H) (-C_D*H[5] + C_E*H[6] - C_F*H[7])
#define HP1(H) ( C_A*H[1] + C_B*H[2] - C_C*H[3])
#define HP2(H) (-C_C*H[4] + C_B*H[5] + C_A*H[6])
#define HP3(H) (-C_F*H[0] + C_E*H[1] - C_D*H[2])

// Scratch (statically allocated)
__device__ float g_y1[128 * 256 * 256];
__device__ float g_y2[128 * 256 * 256];
__device__ float g_z128[128 * 128 * 128];
__device__ float g_z256[128 * 256 * 256];

__device__ __forceinline__ int refl(int i, int n) {
    i = (i < 0) ? (-1 - i) : i;
    return (i >= n) ? (2 * n - 1 - i) : i;
}

__constant__ int cD8[8] = {-4, -2, 0, 2, -1, 1, 3, 5};

// ---------------------------------------------------------------------------
// Stage A: column-direction upsampling level.
//   y1 = ifilt_lp(z) + SH * ifilt_hp(lh_raw)
//   y2 = SH * (ifilt_lp(hl_raw) + ifilt_hp(hh_raw))
// z: (128,r,c) -> y1,y2: (128,2r,c). yh subbands: (r/2, c/2, 2).
// Thread = (b, n, j) computes output rows 4n..4n+3 at column j.
// ---------------------------------------------------------------------------
__global__ void __launch_bounds__(256)
kA(const float* __restrict__ z, const float* __restrict__ yh,
   float* __restrict__ y1, float* __restrict__ y2, int r, int c, int lc, int ln) {
    unsigned idx = blockIdx.x * 256u + threadIdx.x;
    int j = idx & (c - 1);
    int n = (idx >> lc) & ((r >> 1) - 1);
    int b = idx >> (lc + ln);
    int rh = r >> 1;
    int pj = j & 1;

    int rw[8], oB[8];
    float s1v[8], s2v[8];
#pragma unroll
    for (int t = 0; t < 8; t++) {
        int rr = refl(2 * n + cD8[t], r);
        rw[t] = rr;
        int ii = rr >> 1, pi = rr & 1;
        oB[t] = ii * c + (pi ^ pj);
        s1v[t] = (pi & pj) ? -1.f : 1.f;
        s2v[t] = (pi & (pj ^ 1)) ? -1.f : 1.f;
    }

    const float* zb = z + b * r * c + j;
    const float* yb = yh + b * 6 * rh * c + 2 * (j >> 1);
    const int sb = rh * c;

    float L[8], H[8];
#pragma unroll
    for (int t = 0; t < 8; t++) L[t] = __ldg(zb + rw[t] * c);
#pragma unroll
    for (int t = 0; t < 8; t++)
        H[t] = s1v[t] * __ldg(yb + oB[t]) + s2v[t] * __ldg(yb + 5 * sb + oB[t]);  // lh

    float* o1 = y1 + (b * 2 * r + 4 * n) * c + j;
    o1[0]     = LP0(L) + SH * HP0(H);
    o1[c]     = LP1(L) + SH * HP1(H);
    o1[2 * c] = LP2(L) + SH * HP2(H);
    o1[3 * c] = LP3(L) + SH * HP3(H);

#pragma unroll
    for (int t = 0; t < 8; t++)
        L[t] = s1v[t] * __ldg(yb + 2 * sb + oB[t]) + s2v[t] * __ldg(yb + 3 * sb + oB[t]);  // hl
#pragma unroll
    for (int t = 0; t < 8; t++)
        H[t] = s1v[t] * __ldg(yb + 1 * sb + oB[t]) + s2v[t] * __ldg(yb + 4 * sb + oB[t]);  // hh

    float* o2 = y2 + (b * 2 * r + 4 * n) * c + j;
    o2[0]     = SH * (LP0(L) + HP0(H));
    o2[c]     = SH * (LP1(L) + HP1(H));
    o2[2 * c] = SH * (LP2(L) + HP2(H));
    o2[3 * c] = SH * (LP3(L) + HP3(H));
}

// ---------------------------------------------------------------------------
// Stage B: row-direction upsampling. y1 (lowpass), y2 (highpass): (128,R,c)
// -> zo (128,R,2c). Thread = (b, i, n), float4 store at column 4n.
// ---------------------------------------------------------------------------
__global__ void __launch_bounds__(256)
kB(const float* __restrict__ y1, const float* __restrict__ y2,
   float* __restrict__ zo, int R, int c, int lnc, int lR) {
    unsigned idx = blockIdx.x * 256u + threadIdx.x;
    int n = idx & ((c >> 1) - 1);
    int i = (idx >> lnc) & (R - 1);
    int b = idx >> (lnc + lR);

    const float* p1 = y1 + (b * R + i) * c;
    const float* p2 = y2 + (b * R + i) * c;

    float L[8], H[8];
#pragma unroll
    for (int t = 0; t < 8; t++) {
        int cc = refl(2 * n + cD8[t], c);
        L[t] = __ldg(p1 + cc);
        H[t] = __ldg(p2 + cc);
    }
    float4 o;
    o.x = LP0(L) + HP0(H);
    o.y = LP1(L) + HP1(H);
    o.z = LP2(L) + HP2(H);
    o.w = LP3(L) + HP3(H);
    reinterpret_cast<float4*>(zo + (b * R + i) * 2 * c)[n] = o;
}

// ---------------------------------------------------------------------------
// Stage C: final-level column filters (non-decimating, 3/5-tap).
// Thread = (b, m, j) computes output rows i0=2m and i0+1 at column j.
// ---------------------------------------------------------------------------
__global__ void __launch_bounds__(256)
kC(const float* __restrict__ z, const float* __restrict__ yh,
   float* __restrict__ y1, float* __restrict__ y2, int R, int C, int lC, int lm) {
    unsigned idx = blockIdx.x * 256u + threadIdx.x;
    int j = idx & (C - 1);
    int m = (idx >> lC) & ((R >> 1) - 1);
    int b = idx >> (lC + lm);
    int i0 = 2 * m;
    int rh = R >> 1;
    int pj = j & 1;

    int o6[8];
    float s1v[8], s2v[8];
    int rr[6];
#pragma unroll
    for (int t = 0; t < 6; t++) {
        int r = refl(i0 - 2 + t, R);
        rr[t] = r;
        int ii = r >> 1, pi = r & 1;
        o6[t] = ii * C + (pi ^ pj);
        s1v[t] = (pi & pj) ? -1.f : 1.f;
        s2v[t] = (pi & (pj ^ 1)) ? -1.f : 1.f;
    }

    const float* zb = z + b * R * C + j;
    const float* yb = yh + b * 6 * rh * C + 2 * (j >> 1);
    const int sb = rh * C;

    float zr[4];
#pragma unroll
    for (int t = 0; t < 4; t++) zr[t] = __ldg(zb + rr[t + 1] * C);

    float lr[6], hlr[6], hhr[6];
#pragma unroll
    for (int t = 0; t < 6; t++) {
        lr[t]  = s1v[t] * __ldg(yb + o6[t])          + s2v[t] * __ldg(yb + 5 * sb + o6[t]);
        hlr[t] = s1v[t] * __ldg(yb + 2 * sb + o6[t]) + s2v[t] * __ldg(yb + 3 * sb + o6[t]);
        hhr[t] = s1v[t] * __ldg(yb + 1 * sb + o6[t]) + s2v[t] * __ldg(yb + 4 * sb + o6[t]);
    }

    int ob = (b * R + i0) * C + j;
    y1[ob]     = G0 * (zr[0] + zr[2]) + G1 * zr[1]
               + SH * (Q_E * (lr[0] + lr[4]) + Q_D * (lr[1] + lr[3]) + Q_F * lr[2]);
    y1[ob + C] = G0 * (zr[1] + zr[3]) + G1 * zr[2]
               + SH * (Q_E * (lr[1] + lr[5]) + Q_D * (lr[2] + lr[4]) + Q_F * lr[3]);
    y2[ob]     = SH * (G0 * (hlr[1] + hlr[3]) + G1 * hlr[2]
               + Q_E * (hhr[0] + hhr[4]) + Q_D * (hhr[1] + hhr[3]) + Q_F * hhr[2]);
    y2[ob + C] = SH * (G0 * (hlr[2] + hlr[4]) + G1 * hlr[3]
               + Q_E * (hhr[1] + hhr[5]) + Q_D * (hhr[2] + hhr[4]) + Q_F * hhr[3]);
}

// ---------------------------------------------------------------------------
// Stage D: final row filters. out = rowfilter(y1,g0o) + rowfilter(y2,g1o).
// Thread = (b, i, p) computes columns 4p..4p+3 (float4 store).
// ---------------------------------------------------------------------------
__global__ void __launch_bounds__(256)
kD(const float* __restrict__ y1, const float* __restrict__ y2,
   float* __restrict__ out, int R, int C, int lp, int lR) {
    unsigned idx = blockIdx.x * 256u + threadIdx.x;
    int p = idx & ((C >> 2) - 1);
    int i = (idx >> lp) & (R - 1);
    int b = idx >> (lp + lR);
    int j0 = 4 * p;

    const float* r1 = y1 + (b * R + i) * C;
    const float* r2 = y2 + (b * R + i) * C;

    float a[6], v[8];
#pragma unroll
    for (int t = 0; t < 6; t++) a[t] = __ldg(r1 + refl(j0 - 1 + t, C));
#pragma unroll
    for (int t = 0; t < 8; t++) v[t] = __ldg(r2 + refl(j0 - 2 + t, C));

    float4 o;
    o.x = G0 * (a[0] + a[2]) + G1 * a[1] + Q_E * (v[0] + v[4]) + Q_D * (v[1] + v[3]) + Q_F * v[2];
    o.y = G0 * (a[1] + a[3]) + G1 * a[2] + Q_E * (v[1] + v[5]) + Q_D * (v[2] + v[4]) + Q_F * v[3];
    o.z = G0 * (a[2] + a[4]) + G1 * a[3] + Q_E * (v[2] + v[6]) + Q_D * (v[3] + v[5]) + Q_F * v[4];
    o.w = G0 * (a[3] + a[5]) + G1 * a[4] + Q_E * (v[3] + v[7]) + Q_D * (v[4] + v[6]) + Q_F * v[5];
    reinterpret_cast<float4*>(out + (b * R + i) * C)[p] = o;
}

extern "C" void kernel_launch(void* const* d_in, const int* in_sizes, int n_in,
                              void* d_out, int out_size) {
    const float *yl = nullptr, *yh0 = nullptr, *yh1 = nullptr, *yh2 = nullptr;
    for (int i = 0; i < n_in; i++) {
        switch (in_sizes[i]) {
            case 524288:   yl  = (const float*)d_in[i]; break;  // 128*64*64
            case 25165824: yh0 = (const float*)d_in[i]; break;  // 128*6*128*128*2
            case 6291456:  yh1 = (const float*)d_in[i]; break;  // 128*6*64*64*2
            case 1572864:  yh2 = (const float*)d_in[i]; break;  // 128*6*32*32*2
            default: break;
        }
    }

    float *py1, *py2, *pz128, *pz256;
    cudaGetSymbolAddress((void**)&py1,   g_y1);
    cudaGetSymbolAddress((void**)&py2,   g_y2);
    cudaGetSymbolAddress((void**)&pz128, g_z128);
    cudaGetSymbolAddress((void**)&pz256, g_z256);

    // Level with yh2: (64,64) -> (128,128)
    kA<<<128 * 32 * 64 / 256, 256>>>(yl, yh2, py1, py2, 64, 64, 6, 5);
    kB<<<128 * 128 * 32 / 256, 256>>>(py1, py2, pz128, 128, 64, 5, 7);

    // Level with yh1: (128,128) -> (256,256)
    kA<<<128 * 64 * 128 / 256, 256>>>(pz128, yh1, py1, py2, 128, 128, 7, 6);
    kB<<<128 * 256 * 64 / 256, 256>>>(py1, py2, pz256, 256, 128, 6, 8);

    // Final level with yh0 (non-decimating)
    kC<<<128 * 128 * 256 / 256, 256>>>(pz256, yh0, py1, py2, 256, 256, 8, 7);
    kD<<<128 * 256 * 64 / 256, 256>>>(py1, py2, (float*)d_out, 256, 256, 6, 8);
}

// round 3
// speedup vs baseline: 4.3998x; 1.2282x over previous
#include <cuda_runtime.h>

// ---------------------------------------------------------------------------
// Inverse DTCWT, 3 levels, phase-specialized + float2-vectorized.
// Window offsets (around 2n): L/H window index map:
//   [0]=-4 [1]=-2 [2]=0 [3]=+2 [4]=-1 [5]=+1 [6]=+3 [7]=+5
// ---------------------------------------------------------------------------

#define SH   0.70710678118654752440f
#define C_A  0.23389032f
#define C_B  0.5875183f
#define C_C  0.11430184f
#define C_D  0.76027237f
#define C_E  0.08832942f
#define C_F  0.03516384f

#define G0   0.35355339059327f
#define G1   0.70710678118655f
#define Q_E  (-0.08838834764832f)
#define Q_D  (-0.17677669529664f)
#define Q_F  0.53033008588991f

#define LP0(L) ( C_A*L[1] + C_B*L[2] - C_C*L[3])
#define LP1(L) ( C_D*L[5] - C_E*L[6] + C_F*L[7])
#define LP2(L) ( C_F*L[0] - C_E*L[1] + C_D*L[2])
#define LP3(L) (-C_C*L[4] + C_B*L[5] + C_A*L[6])
#define HP0(H) (-C_D*H[5] + C_E*H[6] - C_F*H[7])
#define HP1(H) ( C_A*H[1] + C_B*H[2] - C_C*H[3])
#define HP2(H) (-C_C*H[4] + C_B*H[5] + C_A*H[6])
#define HP3(H) (-C_F*H[0] + C_E*H[1] - C_D*H[2])

__device__ float g_y1[128 * 256 * 256];
__device__ float g_y2[128 * 256 * 256];
__device__ float g_z128[128 * 128 * 128];
__device__ float g_z256[128 * 256 * 256];

__device__ __forceinline__ int refl(int i, int n) {
    i = (i < 0) ? (-1 - i) : i;
    return (i >= n) ? (2 * n - 1 - i) : i;
}

__constant__ int cD8[8] = {-4, -2, 0, 2, -1, 1, 3, 5};

// ---------------- slow-path helpers (verbatim R2 logic, per column) --------
__device__ void kA_slow_col(const float* __restrict__ z, const float* __restrict__ yh,
                            float* __restrict__ y1, float* __restrict__ y2,
                            int r, int c, int b, int n, int j) {
    int rh = r >> 1;
    int pj = j & 1;
    int rw[8], oB[8];
    float s1v[8], s2v[8];
#pragma unroll
    for (int t = 0; t < 8; t++) {
        int rr = refl(2 * n + cD8[t], r);
        rw[t] = rr;
        int ii = rr >> 1, pi = rr & 1;
        oB[t] = ii * c + (pi ^ pj);
        s1v[t] = (pi & pj) ? -1.f : 1.f;
        s2v[t] = (pi & (pj ^ 1)) ? -1.f : 1.f;
    }
    const float* zb = z + b * r * c + j;
    const float* yb = yh + b * 6 * rh * c + 2 * (j >> 1);
    const int sb = rh * c;

    float L[8], H[8];
#pragma unroll
    for (int t = 0; t < 8; t++) L[t] = __ldg(zb + rw[t] * c);
#pragma unroll
    for (int t = 0; t < 8; t++)
        H[t] = s1v[t] * __ldg(yb + oB[t]) + s2v[t] * __ldg(yb + 5 * sb + oB[t]);

    float* o1 = y1 + (b * 2 * r + 4 * n) * c + j;
    o1[0]     = LP0(L) + SH * HP0(H);
    o1[c]     = LP1(L) + SH * HP1(H);
    o1[2 * c] = LP2(L) + SH * HP2(H);
    o1[3 * c] = LP3(L) + SH * HP3(H);

#pragma unroll
    for (int t = 0; t < 8; t++)
        L[t] = s1v[t] * __ldg(yb + 2 * sb + oB[t]) + s2v[t] * __ldg(yb + 3 * sb + oB[t]);
#pragma unroll
    for (int t = 0; t < 8; t++)
        H[t] = s1v[t] * __ldg(yb + 1 * sb + oB[t]) + s2v[t] * __ldg(yb + 4 * sb + oB[t]);

    float* o2 = y2 + (b * 2 * r + 4 * n) * c + j;
    o2[0]     = SH * (LP0(L) + HP0(H));
    o2[c]     = SH * (LP1(L) + HP1(H));
    o2[2 * c] = SH * (LP2(L) + HP2(H));
    o2[3 * c] = SH * (LP3(L) + HP3(H));
}

__device__ void kC_slow_col(const float* __restrict__ z, const float* __restrict__ yh,
                            float* __restrict__ y1, float* __restrict__ y2,
                            int R, int C, int b, int m, int j) {
    int i0 = 2 * m;
    int rh = R >> 1;
    int pj = j & 1;
    int o6[6];
    float s1v[6], s2v[6];
    int rr[6];
#pragma unroll
    for (int t = 0; t < 6; t++) {
        int rx = refl(i0 - 2 + t, R);
        rr[t] = rx;
        int ii = rx >> 1, pi = rx & 1;
        o6[t] = ii * C + (pi ^ pj);
        s1v[t] = (pi & pj) ? -1.f : 1.f;
        s2v[t] = (pi & (pj ^ 1)) ? -1.f : 1.f;
    }
    const float* zb = z + b * R * C + j;
    const float* yb = yh + b * 6 * rh * C + 2 * (j >> 1);
    const int sb = rh * C;

    float zr[4];
#pragma unroll
    for (int t = 0; t < 4; t++) zr[t] = __ldg(zb + rr[t + 1] * C);

    float lr[6], hlr[6], hhr[6];
#pragma unroll
    for (int t = 0; t < 6; t++) {
        lr[t]  = s1v[t] * __ldg(yb + o6[t])          + s2v[t] * __ldg(yb + 5 * sb + o6[t]);
        hlr[t] = s1v[t] * __ldg(yb + 2 * sb + o6[t]) + s2v[t] * __ldg(yb + 3 * sb + o6[t]);
        hhr[t] = s1v[t] * __ldg(yb + 1 * sb + o6[t]) + s2v[t] * __ldg(yb + 4 * sb + o6[t]);
    }
    int ob = (b * R + i0) * C + j;
    y1[ob]     = G0 * (zr[0] + zr[2]) + G1 * zr[1]
               + SH * (Q_E * (lr[0] + lr[4]) + Q_D * (lr[1] + lr[3]) + Q_F * lr[2]);
    y1[ob + C] = G0 * (zr[1] + zr[3]) + G1 * zr[2]
               + SH * (Q_E * (lr[1] + lr[5]) + Q_D * (lr[2] + lr[4]) + Q_F * lr[3]);
    y2[ob]     = SH * (G0 * (hlr[1] + hlr[3]) + G1 * hlr[2]
               + Q_E * (hhr[0] + hhr[4]) + Q_D * (hhr[1] + hhr[3]) + Q_F * hhr[2]);
    y2[ob + C] = SH * (G0 * (hlr[2] + hlr[4]) + G1 * hlr[3]
               + Q_E * (hhr[1] + hhr[5]) + Q_D * (hhr[2] + hhr[4]) + Q_F * hhr[3]);
}

// ---------------------------------------------------------------------------
// Stage A: column upsampling, thread = (b, n, jj) -> columns 2jj, 2jj+1,
// output rows 4n..4n+3 of y1 and y2 (float2 stores).
// ---------------------------------------------------------------------------
__global__ void __launch_bounds__(256)
kA(const float* __restrict__ z, const float* __restrict__ yh,
   float* __restrict__ y1, float* __restrict__ y2, int r, int c, int ljj, int ln) {
    unsigned idx = blockIdx.x * 256u + threadIdx.x;
    int ch = c >> 1, rh = r >> 1;
    int jj = idx & (ch - 1);
    int n = (idx >> ljj) & (rh - 1);
    int b = idx >> (ljj + ln);

    if (n < 2 || n > rh - 3) {  // boundary: warp-uniform slow path
        kA_slow_col(z, yh, y1, y2, r, c, b, n, 2 * jj);
        kA_slow_col(z, yh, y1, y2, r, c, b, n, 2 * jj + 1);
        return;
    }

    const float2* z2 = (const float2*)z + b * r * ch + jj;
    const float2* yb2 = (const float2*)yh + b * 6 * rh * ch + jj;
    const int sstr = rh * ch;

    // z window rows: 2n + {-4,-2,0,2,-1,1,3,5}
    float2 Lz[8];
    {
        int base = 2 * n;
        Lz[0] = __ldg(z2 + (base - 4) * ch);
        Lz[1] = __ldg(z2 + (base - 2) * ch);
        Lz[2] = __ldg(z2 + base * ch);
        Lz[3] = __ldg(z2 + (base + 2) * ch);
        Lz[4] = __ldg(z2 + (base - 1) * ch);
        Lz[5] = __ldg(z2 + (base + 1) * ch);
        Lz[6] = __ldg(z2 + (base + 3) * ch);
        Lz[7] = __ldg(z2 + (base + 5) * ch);
    }
    float L0[8], L1[8];
#pragma unroll
    for (int t = 0; t < 8; t++) { L0[t] = Lz[t].x; L1[t] = Lz[t].y; }

    // band pair loader: subband rows ii = n-2..n+2 (interior => no reflection)
    //   even slots [0..3] rows 2n+{-4,-2,0,2} pi=0 ; odd slots [4..7] rows
    //   2n+{-1,1,3,5} pi=1
#define LOAD_PAIR5(S1, S2, B0, B1)                                            \
    {                                                                         \
        float2 w1[5], w2[5];                                                  \
        _Pragma("unroll") for (int t = 0; t < 5; t++) {                       \
            w1[t] = __ldg(yb2 + ((S1) * sstr + (n - 2 + t) * ch));            \
            w2[t] = __ldg(yb2 + ((S2) * sstr + (n - 2 + t) * ch));            \
        }                                                                     \
        _Pragma("unroll") for (int t = 0; t < 4; t++) {                       \
            B0[t] = w1[t].x + w2[t].x;                                        \
            B1[t] = w1[t].y + w2[t].y;                                        \
            B0[4 + t] = w1[t + 1].y - w2[t + 1].y;                            \
            B1[4 + t] = w2[t + 1].x - w1[t + 1].x;                            \
        }                                                                     \
    }

    float2* o1 = (float2*)y1 + (b * 2 * r + 4 * n) * ch + jj;
    {
        float B0[8], B1[8];
        LOAD_PAIR5(0, 5, B0, B1);  // lh
        float2 o;
        o.x = LP0(L0) + SH * HP0(B0); o.y = LP0(L1) + SH * HP0(B1); o1[0] = o;
        o.x = LP1(L0) + SH * HP1(B0); o.y = LP1(L1) + SH * HP1(B1); o1[ch] = o;
        o.x = LP2(L0) + SH * HP2(B0); o.y = LP2(L1) + SH * HP2(B1); o1[2 * ch] = o;
        o.x = LP3(L0) + SH * HP3(B0); o.y = LP3(L1) + SH * HP3(B1); o1[3 * ch] = o;
    }
    float2* o2 = (float2*)y2 + (b * 2 * r + 4 * n) * ch + jj;
    {
        float A0[8], A1[8], B0[8], B1[8];
        LOAD_PAIR5(2, 3, A0, A1);  // hl (lowpass source)
        LOAD_PAIR5(1, 4, B0, B1);  // hh (highpass source)
        float2 o;
        o.x = SH * (LP0(A0) + HP0(B0)); o.y = SH * (LP0(A1) + HP0(B1)); o2[0] = o;
        o.x = SH * (LP1(A0) + HP1(B0)); o.y = SH * (LP1(A1) + HP1(B1)); o2[ch] = o;
        o.x = SH * (LP2(A0) + HP2(B0)); o.y = SH * (LP2(A1) + HP2(B1)); o2[2 * ch] = o;
        o.x = SH * (LP3(A0) + HP3(B0)); o.y = SH * (LP3(A1) + HP3(B1)); o2[3 * ch] = o;
    }
#undef LOAD_PAIR5
}

// ---------------------------------------------------------------------------
// Stage B: row upsampling. Thread = (b, i, n): float4 store at column 4n.
// ---------------------------------------------------------------------------
__global__ void __launch_bounds__(256)
kB(const float* __restrict__ y1, const float* __restrict__ y2,
   float* __restrict__ zo, int R, int c, int lnc, int lR) {
    unsigned idx = blockIdx.x * 256u + threadIdx.x;
    int ch = c >> 1;
    int n = idx & (ch - 1);
    int i = (idx >> lnc) & (R - 1);
    int b = idx >> (lnc + lR);

    float L[8], H[8];
    if (n >= 2 && n <= ch - 3) {
        const float2* q1 = (const float2*)y1 + (b * R + i) * ch + (n - 2);
        const float2* q2 = (const float2*)y2 + (b * R + i) * ch + (n - 2);
        float2 u0 = __ldg(q1), u1 = __ldg(q1 + 1), u2 = __ldg(q1 + 2),
               u3 = __ldg(q1 + 3), u4 = __ldg(q1 + 4);
        float2 w0 = __ldg(q2), w1 = __ldg(q2 + 1), w2 = __ldg(q2 + 2),
               w3 = __ldg(q2 + 3), w4 = __ldg(q2 + 4);
        L[0] = u0.x; L[1] = u1.x; L[2] = u2.x; L[3] = u3.x;
        L[4] = u1.y; L[5] = u2.y; L[6] = u3.y; L[7] = u4.y;
        H[0] = w0.x; H[1] = w1.x; H[2] = w2.x; H[3] = w3.x;
        H[4] = w1.y; H[5] = w2.y; H[6] = w3.y; H[7] = w4.y;
    } else {
        const float* p1 = y1 + (b * R + i) * c;
        const float* p2 = y2 + (b * R + i) * c;
#pragma unroll
        for (int t = 0; t < 8; t++) {
            int cc = refl(2 * n + cD8[t], c);
            L[t] = __ldg(p1 + cc);
            H[t] = __ldg(p2 + cc);
        }
    }
    float4 o;
    o.x = LP0(L) + HP0(H);
    o.y = LP1(L) + HP1(H);
    o.z = LP2(L) + HP2(H);
    o.w = LP3(L) + HP3(H);
    reinterpret_cast<float4*>(zo + (b * R + i) * 2 * c)[n] = o;
}

// ---------------------------------------------------------------------------
// Stage C: final-level column filters. Thread = (b, m, jj): columns 2jj,2jj+1,
// rows 2m, 2m+1 of y1 and y2 (float2 stores).
// ---------------------------------------------------------------------------
__global__ void __launch_bounds__(256)
kC(const float* __restrict__ z, const float* __restrict__ yh,
   float* __restrict__ y1, float* __restrict__ y2, int R, int C, int ljj, int lm) {
    unsigned idx = blockIdx.x * 256u + threadIdx.x;
    int ch = C >> 1, rh = R >> 1;
    int jj = idx & (ch - 1);
    int m = (idx >> ljj) & (rh - 1);
    int b = idx >> (ljj + lm);

    if (m < 1 || m > rh - 2) {
        kC_slow_col(z, yh, y1, y2, R, C, b, m, 2 * jj);
        kC_slow_col(z, yh, y1, y2, R, C, b, m, 2 * jj + 1);
        return;
    }
    int i0 = 2 * m;
    const float2* z2 = (const float2*)z + b * R * ch + jj;
    const float2* yb2 = (const float2*)yh + b * 6 * rh * ch + jj;
    const int sstr = rh * ch;

    float2 zr[4];  // rows i0-1..i0+2
#pragma unroll
    for (int t = 0; t < 4; t++) zr[t] = __ldg(z2 + (i0 - 1 + t) * ch);

    // band pair: subband rows ii = m-1..m+1; window slots [0..5] rows i0-2..i0+3
#define LOAD_PAIR3(S1, S2, B0, B1)                                            \
    {                                                                         \
        float2 w1[3], w2[3];                                                  \
        _Pragma("unroll") for (int t = 0; t < 3; t++) {                       \
            w1[t] = __ldg(yb2 + ((S1) * sstr + (m - 1 + t) * ch));            \
            w2[t] = __ldg(yb2 + ((S2) * sstr + (m - 1 + t) * ch));            \
        }                                                                     \
        _Pragma("unroll") for (int t = 0; t < 3; t++) {                       \
            B0[2 * t] = w1[t].x + w2[t].x;                                    \
            B1[2 * t] = w1[t].y + w2[t].y;                                    \
            B0[2 * t + 1] = w1[t].y - w2[t].y;                                \
            B1[2 * t + 1] = w2[t].x - w1[t].x;                                \
        }                                                                     \
    }

    float lr0[6], lr1[6], hl0[6], hl1[6], hh0[6], hh1[6];
    LOAD_PAIR3(0, 5, lr0, lr1);
    LOAD_PAIR3(2, 3, hl0, hl1);
    LOAD_PAIR3(1, 4, hh0, hh1);
#undef LOAD_PAIR3

    float2* o1 = (float2*)y1 + (b * R + i0) * ch + jj;
    float2* o2 = (float2*)y2 + (b * R + i0) * ch + jj;
    float2 o;
    o.x = G0 * (zr[0].x + zr[2].x) + G1 * zr[1].x
        + SH * (Q_E * (lr0[0] + lr0[4]) + Q_D * (lr0[1] + lr0[3]) + Q_F * lr0[2]);
    o.y = G0 * (zr[0].y + zr[2].y) + G1 * zr[1].y
        + SH * (Q_E * (lr1[0] + lr1[4]) + Q_D * (lr1[1] + lr1[3]) + Q_F * lr1[2]);
    o1[0] = o;
    o.x = G0 * (zr[1].x + zr[3].x) + G1 * zr[2].x
        + SH * (Q_E * (lr0[1] + lr0[5]) + Q_D * (lr0[2] + lr0[4]) + Q_F * lr0[3]);
    o.y = G0 * (zr[1].y + zr[3].y) + G1 * zr[2].y
        + SH * (Q_E * (lr1[1] + lr1[5]) + Q_D * (lr1[2] + lr1[4]) + Q_F * lr1[3]);
    o1[ch] = o;
    o.x = SH * (G0 * (hl0[1] + hl0[3]) + G1 * hl0[2]
        + Q_E * (hh0[0] + hh0[4]) + Q_D * (hh0[1] + hh0[3]) + Q_F * hh0[2]);
    o.y = SH * (G0 * (hl1[1] + hl1[3]) + G1 * hl1[2]
        + Q_E * (hh1[0] + hh1[4]) + Q_D * (hh1[1] + hh1[3]) + Q_F * hh1[2]);
    o2[0] = o;
    o.x = SH * (G0 * (hl0[2] + hl0[4]) + G1 * hl0[3]
        + Q_E * (hh0[1] + hh0[5]) + Q_D * (hh0[2] + hh0[4]) + Q_F * hh0[3]);
    o.y = SH * (G0 * (hl1[2] + hl1[4]) + G1 * hl1[3]
        + Q_E * (hh1[1] + hh1[5]) + Q_D * (hh1[2] + hh1[4]) + Q_F * hh1[3]);
    o2[ch] = o;
}

// ---------------------------------------------------------------------------
// Stage D: final row filters. Thread = (b, i, p): columns 4p..4p+3.
// ---------------------------------------------------------------------------
__global__ void __launch_bounds__(256)
kD(const float* __restrict__ y1, const float* __restrict__ y2,
   float* __restrict__ out, int R, int C, int lp, int lR) {
    unsigned idx = blockIdx.x * 256u + threadIdx.x;
    int p = idx & ((C >> 2) - 1);
    int i = (idx >> lp) & (R - 1);
    int b = idx >> (lp + lR);
    int j0 = 4 * p;

    float a[6], v[8];
    if (p >= 1 && p <= ((C - 6) >> 2)) {
        const float2* q1 = (const float2*)y1 + (b * R + i) * (C >> 1) + (2 * p - 1);
        const float2* q2 = (const float2*)y2 + (b * R + i) * (C >> 1) + (2 * p - 1);
        float2 f0 = __ldg(q1), f1 = __ldg(q1 + 1), f2 = __ldg(q1 + 2), f3 = __ldg(q1 + 3);
        float2 g0 = __ldg(q2), g1 = __ldg(q2 + 1), g2 = __ldg(q2 + 2), g3 = __ldg(q2 + 3);
        a[0] = f0.y; a[1] = f1.x; a[2] = f1.y; a[3] = f2.x; a[4] = f2.y; a[5] = f3.x;
        v[0] = g0.x; v[1] = g0.y; v[2] = g1.x; v[3] = g1.y;
        v[4] = g2.x; v[5] = g2.y; v[6] = g3.x; v[7] = g3.y;
    } else {
        const float* r1 = y1 + (b * R + i) * C;
        const float* r2 = y2 + (b * R + i) * C;
#pragma unroll
        for (int t = 0; t < 6; t++) a[t] = __ldg(r1 + refl(j0 - 1 + t, C));
#pragma unroll
        for (int t = 0; t < 8; t++) v[t] = __ldg(r2 + refl(j0 - 2 + t, C));
    }
    float4 o;
    o.x = G0 * (a[0] + a[2]) + G1 * a[1] + Q_E * (v[0] + v[4]) + Q_D * (v[1] + v[3]) + Q_F * v[2];
    o.y = G0 * (a[1] + a[3]) + G1 * a[2] + Q_E * (v[1] + v[5]) + Q_D * (v[2] + v[4]) + Q_F * v[3];
    o.z = G0 * (a[2] + a[4]) + G1 * a[3] + Q_E * (v[2] + v[6]) + Q_D * (v[3] + v[5]) + Q_F * v[4];
    o.w = G0 * (a[3] + a[5]) + G1 * a[4] + Q_E * (v[3] + v[7]) + Q_D * (v[4] + v[6]) + Q_F * v[5];
    reinterpret_cast<float4*>(out + (b * R + i) * C)[p] = o;
}

extern "C" void kernel_launch(void* const* d_in, const int* in_sizes, int n_in,
                              void* d_out, int out_size) {
    const float *yl = nullptr, *yh0 = nullptr, *yh1 = nullptr, *yh2 = nullptr;
    for (int i = 0; i < n_in; i++) {
        switch (in_sizes[i]) {
            case 524288:   yl  = (const float*)d_in[i]; break;  // 128*64*64
            case 25165824: yh0 = (const float*)d_in[i]; break;  // 128*6*128*128*2
            case 6291456:  yh1 = (const float*)d_in[i]; break;  // 128*6*64*64*2
            case 1572864:  yh2 = (const float*)d_in[i]; break;  // 128*6*32*32*2
            default: break;
        }
    }

    float *py1, *py2, *pz128, *pz256;
    cudaGetSymbolAddress((void**)&py1,   g_y1);
    cudaGetSymbolAddress((void**)&py2,   g_y2);
    cudaGetSymbolAddress((void**)&pz128, g_z128);
    cudaGetSymbolAddress((void**)&pz256, g_z256);

    // Level with yh2: (64,64) -> (128,128).  kA threads: b*rh*ch = 128*32*32
    kA<<<128 * 32 * 32 / 256, 256>>>(yl, yh2, py1, py2, 64, 64, 5, 5);
    kB<<<128 * 128 * 32 / 256, 256>>>(py1, py2, pz128, 128, 64, 5, 7);

    // Level with yh1: (128,128) -> (256,256). kA threads: 128*64*64
    kA<<<128 * 64 * 64 / 256, 256>>>(pz128, yh1, py1, py2, 128, 128, 6, 6);
    kB<<<128 * 256 * 64 / 256, 256>>>(py1, py2, pz256, 256, 128, 6, 8);

    // Final level with yh0. kC threads: 128*128*128
    kC<<<128 * 128 * 128 / 256, 256>>>(pz256, yh0, py1, py2, 256, 256, 7, 7);
    kD<<<128 * 256 * 64 / 256, 256>>>(py1, py2, (float*)d_out, 256, 256, 6, 8);
}